// round 5
// baseline (speedup 1.0000x reference)
#include <cuda_runtime.h>
#include <cuda_bf16.h>
#include <cstdint>
#include <math.h>

// ---------------- problem sizes ----------------
#define BD   512
#define DD   2048
#define NTOT (BD*DD)
#define NV   (NTOT/4)      // 262144
#define WTOT (DD*DD)
#define WV   (WTOT/4)      // 1048576

#define MAX_STEPS 32
#define TOLC      0.01f
#define SPEED_TOL 1e-3f
#define DT0       0.1f
#define MIN_DT    0.1f

#define EW_BLK  256
#define EW_GRID (NV / EW_BLK)   // 1024

// ---------------- device state ----------------
__device__ float g_X [NTOT];   // buffer 0
__device__ float g_X5[NTOT];   // buffer 1
__device__ float g_XS[NTOT];   // stage input (stages 2-6)
__device__ __nv_bfloat16 g_Ah[NTOT];       // stage 2-6 split
__device__ __nv_bfloat16 g_Al[NTOT];
__device__ __nv_bfloat16 g_AhX[2][NTOT];   // split of reflect(current x), double buffered
__device__ __nv_bfloat16 g_AlX[2][NTOT];
__device__ __nv_bfloat16 g_Wh[WTOT];
__device__ __nv_bfloat16 g_Wl[WTOT];
__device__ float g_K [6][NTOT];
__device__ float g_dt;
__device__ int   g_done;
__device__ int   g_cur;            // 0: g_X current, 1: g_X5 current
__device__ unsigned int g_err_bits;
__device__ unsigned int g_spd_bits;
__device__ unsigned int g_cnt;
__device__ __nv_bfloat16* g_pAh;   // = g_AhX[g_cur]
__device__ __nv_bfloat16* g_pAl;
__device__ float*         g_pXS;   // = current x buffer

// ---------------- helpers ----------------
__device__ __forceinline__ float reflect_f(float x) {
    int i = (int)x;
    return ((i & 1) == 0) ? x : 1.0f - x;
}
__device__ __forceinline__ void axpy4(float4& x, float c, const float4 k) {
    x.x += c * k.x; x.y += c * k.y; x.z += c * k.z; x.w += c * k.w;
}
__device__ __forceinline__ uint32_t smem_u32(const void* p) {
    uint32_t a;
    asm("{ .reg .u64 t; cvta.to.shared.u64 t, %1; cvt.u32.u64 %0, t; }" : "=r"(a) : "l"(p));
    return a;
}
__device__ __forceinline__ void cp16(uint32_t dst, const void* src) {
    asm volatile("cp.async.cg.shared.global [%0], [%1], 16;" :: "r"(dst), "l"(src));
}
__device__ __forceinline__ void cp_commit() { asm volatile("cp.async.commit_group;" ::: "memory"); }
template <int N> __device__ __forceinline__ void cp_wait() {
    asm volatile("cp.async.wait_group %0;" :: "n"(N) : "memory");
}
__device__ __forceinline__ void ldsm4(uint32_t* r, uint32_t addr) {
    asm volatile("ldmatrix.sync.aligned.m8n8.x4.shared.b16 {%0,%1,%2,%3}, [%4];"
                 : "=r"(r[0]), "=r"(r[1]), "=r"(r[2]), "=r"(r[3]) : "r"(addr));
}
__device__ __forceinline__ void mma16816(float* c, const uint32_t* a, const uint32_t* b) {
    asm("mma.sync.aligned.m16n8k16.row.col.f32.bf16.bf16.f32 "
        "{%0,%1,%2,%3}, {%4,%5,%6,%7}, {%8,%9}, {%0,%1,%2,%3};"
        : "+f"(c[0]), "+f"(c[1]), "+f"(c[2]), "+f"(c[3])
        : "r"(a[0]), "r"(a[1]), "r"(a[2]), "r"(a[3]), "r"(b[0]), "r"(b[1]));
}
__device__ __forceinline__ void split_bf16(float y, __nv_bfloat16& h, __nv_bfloat16& l) {
    h = __float2bfloat16_rn(y);
    l = __float2bfloat16_rn(y - __bfloat162float(h));
}

// ---------------- init / split ----------------
__global__ void k_splitW(const float* __restrict__ W) {
    int i = blockIdx.x * blockDim.x + threadIdx.x;   // grid covers WV exactly
    float4 w = ((const float4*)W)[i];
    __nv_bfloat16 h[4], l[4];
    float v[4] = {w.x, w.y, w.z, w.w};
#pragma unroll
    for (int c = 0; c < 4; c++) split_bf16(v[c], h[c], l[c]);
    *(uint2*)&g_Wh[i * 4] = *(uint2*)h;
    *(uint2*)&g_Wl[i * 4] = *(uint2*)l;
}

__global__ void k_init(const float* __restrict__ x0) {
    int i = blockIdx.x * blockDim.x + threadIdx.x;   // grid covers NV exactly
    float4 x = ((const float4*)x0)[i];
    ((float4*)g_X)[i] = x;
    float v[4] = {x.x, x.y, x.z, x.w};
    __nv_bfloat16 h[4], l[4];
#pragma unroll
    for (int c = 0; c < 4; c++) split_bf16(reflect_f(v[c]), h[c], l[c]);
    *(uint2*)&g_AhX[0][i * 4] = *(uint2*)h;
    *(uint2*)&g_AlX[0][i * 4] = *(uint2*)l;
    if (i == 0) {
        g_dt = DT0; g_done = 0; g_cur = 0;
        g_err_bits = 0u; g_spd_bits = 0u; g_cnt = 0u;
        g_pAh = g_AhX[0]; g_pAl = g_AlX[0]; g_pXS = g_X;
    }
}

// ---------------- stage prep (stages 2-6): XS = cur + dt*sum a_i K_i ----------------
template <int NK>
__global__ void k_stage(float a0, float a1, float a2, float a3, float a4) {
    if (g_done) return;
    float dt = g_dt;
    const float4* X4 = (const float4*)(g_cur ? g_X5 : g_X);
    int i = blockIdx.x * blockDim.x + threadIdx.x;
    float4 xs = X4[i];
    if (NK >= 1) axpy4(xs, dt * a0, ((const float4*)g_K[0])[i]);
    if (NK >= 2) axpy4(xs, dt * a1, ((const float4*)g_K[1])[i]);
    if (NK >= 3) axpy4(xs, dt * a2, ((const float4*)g_K[2])[i]);
    if (NK >= 4) axpy4(xs, dt * a3, ((const float4*)g_K[3])[i]);
    if (NK >= 5) axpy4(xs, dt * a4, ((const float4*)g_K[4])[i]);
    float v[4] = {xs.x, xs.y, xs.z, xs.w};
    __nv_bfloat16 h[4], l[4];
#pragma unroll
    for (int c = 0; c < 4; c++) split_bf16(reflect_f(v[c]), h[c], l[c]);
    ((float4*)g_XS)[i] = xs;
    *(uint2*)&g_Ah[i * 4] = *(uint2*)h;
    *(uint2*)&g_Al[i * 4] = *(uint2*)l;
}

// ---------------- mma.sync GEMM: K[kidx] = sign(XS) * (r(XS) @ W + b) ----------------
// bf16x3. CTA tile 128x64x64; 16 warps = 8 spatial (warp 32x32) x 2 k-groups.
#define BMT 128
#define BNT 64
#define BKC 64
#define NITER (DD / BKC)       // 32
#define PITCH 144              // 128B data + 16B pad
#define AH_OFF 0
#define AL_OFF (128 * PITCH)
#define BH_OFF (2 * 128 * PITCH)
#define BL_OFF (2 * 128 * PITCH + 64 * PITCH)
#define STAGE  (2 * 128 * PITCH + 2 * 64 * PITCH)  // 55296
#define GEMM_SMEM (4 * STAGE)  // 221184

__device__ __forceinline__ void load_stage(uint32_t sbase, int k0, int bm, int bn, int tid,
                                           const __nv_bfloat16* Ahp, const __nv_bfloat16* Alp) {
#pragma unroll
    for (int i = 0; i < 2; i++) {
        int ch = tid + i * 512;          // 1024 chunks: 128 rows x 8
        int r = ch >> 3, c = ch & 7;
        uint32_t off = (uint32_t)(r * PITCH + c * 16);
        size_t go = (size_t)(bm + r) * DD + k0 + c * 8;
        cp16(sbase + AH_OFF + off, Ahp + go);
        cp16(sbase + AL_OFF + off, Alp + go);
    }
    {
        int r = tid >> 3, c = tid & 7;   // 512 chunks: 64 rows x 8
        uint32_t off = (uint32_t)(r * PITCH + c * 16);
        size_t go = (size_t)(bn + r) * DD + k0 + c * 8;
        cp16(sbase + BH_OFF + off, g_Wh + go);
        cp16(sbase + BL_OFF + off, g_Wl + go);
    }
    cp_commit();
}

__global__ __launch_bounds__(512, 1)
void k_gemm_pvf(const float* __restrict__ bias, int kidx, int use_cur) {
    if (g_done) return;
    extern __shared__ char smem[];
    uint32_t sb = smem_u32(smem);
    const int tid  = threadIdx.x;
    const int wid  = tid >> 5;
    const int lane = tid & 31;
    const int wk   = wid >> 3;      // 0/1 k-group
    const int ws   = wid & 7;       // spatial warp id
    const int wm   = ws >> 1;       // 0..3 -> 32 rows each
    const int wn   = ws & 1;        // 0..1 -> 32 cols each
    const int bm   = blockIdx.y * BMT;
    const int bn   = blockIdx.x * BNT;

    const __nv_bfloat16* Ahp = use_cur ? g_pAh : g_Ah;
    const __nv_bfloat16* Alp = use_cur ? g_pAl : g_Al;

    float acc[2][4][4];
#pragma unroll
    for (int mt = 0; mt < 2; mt++)
#pragma unroll
        for (int nt = 0; nt < 4; nt++)
#pragma unroll
            for (int c = 0; c < 4; c++) acc[mt][nt][c] = 0.0f;

    load_stage(sb + 0 * STAGE, 0 * BKC, bm, bn, tid, Ahp, Alp);
    load_stage(sb + 1 * STAGE, 1 * BKC, bm, bn, tid, Ahp, Alp);
    load_stage(sb + 2 * STAGE, 2 * BKC, bm, bn, tid, Ahp, Alp);

    const int g  = lane >> 3;
    const int l7 = lane & 7;
    const uint32_t offA0 = (uint32_t)((wm * 32 + ((g & 1) << 3) + l7) * PITCH + (g >> 1) * 16);
    const uint32_t offA1 = offA0 + 16 * PITCH;
    const uint32_t offB0 = (uint32_t)((wn * 32 + ((g >> 1) << 3) + l7) * PITCH + (g & 1) * 16);
    const uint32_t offB1 = offB0 + 16 * PITCH;
    const uint32_t kbase = (uint32_t)(wk * 64);   // 2 k16-slices * 32B per group

    for (int it = 0; it < NITER; ++it) {
        if (it < NITER - 2)       cp_wait<2>();
        else if (it == NITER - 2) cp_wait<1>();
        else                      cp_wait<0>();
        __syncthreads();

        int J = it + 3;
        if (J < NITER)
            load_stage(sb + (uint32_t)((J & 3) * STAGE), J * BKC, bm, bn, tid, Ahp, Alp);

        uint32_t stg = sb + (uint32_t)((it & 3) * STAGE);
#pragma unroll
        for (int s = 0; s < 2; s++) {
            uint32_t koff = kbase + (uint32_t)(s * 32);
            uint32_t ah0[4], ah1[4], al0[4], al1[4], bh[2][4], bl[2][4];
            ldsm4(ah0, stg + AH_OFF + offA0 + koff);
            ldsm4(ah1, stg + AH_OFF + offA1 + koff);
            ldsm4(al0, stg + AL_OFF + offA0 + koff);
            ldsm4(al1, stg + AL_OFF + offA1 + koff);
            ldsm4(bh[0], stg + BH_OFF + offB0 + koff);
            ldsm4(bh[1], stg + BH_OFF + offB1 + koff);
            ldsm4(bl[0], stg + BL_OFF + offB0 + koff);
            ldsm4(bl[1], stg + BL_OFF + offB1 + koff);
#pragma unroll
            for (int nt = 0; nt < 4; nt++) {
                const uint32_t* bhp = &bh[nt >> 1][(nt & 1) * 2];
                const uint32_t* blp = &bl[nt >> 1][(nt & 1) * 2];
                mma16816(acc[0][nt], ah0, bhp);
                mma16816(acc[0][nt], ah0, blp);
                mma16816(acc[0][nt], al0, bhp);
                mma16816(acc[1][nt], ah1, bhp);
                mma16816(acc[1][nt], ah1, blp);
                mma16816(acc[1][nt], al1, bhp);
            }
        }
    }

    // ---- k-group reduction via smem (reuse tile buffers) ----
    __syncthreads();
    float* red = (float*)smem;
    if (wk == 1) {
#pragma unroll
        for (int mt = 0; mt < 2; mt++)
#pragma unroll
            for (int nt = 0; nt < 4; nt++)
#pragma unroll
                for (int c = 0; c < 4; c++)
                    red[ws * 1024 + ((mt * 4 + nt) * 4 + c) * 32 + lane] = acc[mt][nt][c];
    }
    __syncthreads();
    if (wk == 0) {
#pragma unroll
        for (int mt = 0; mt < 2; mt++)
#pragma unroll
            for (int nt = 0; nt < 4; nt++)
#pragma unroll
                for (int c = 0; c < 4; c++)
                    acc[mt][nt][c] += red[ws * 1024 + ((mt * 4 + nt) * 4 + c) * 32 + lane];

        const float* XSp = use_cur ? g_pXS : g_XS;
        float* Kout = g_K[kidx];
#pragma unroll
        for (int mt = 0; mt < 2; mt++) {
            int m0 = bm + wm * 32 + mt * 16 + (lane >> 2);
#pragma unroll
            for (int nt = 0; nt < 4; nt++) {
                int n0 = bn + wn * 32 + nt * 8 + 2 * (lane & 3);
                float2 bv = *(const float2*)&bias[n0];
#pragma unroll
                for (int half = 0; half < 2; half++) {
                    int m = m0 + half * 8;
                    float2 xs = *(const float2*)&XSp[(size_t)m * DD + n0];
                    float v0 = acc[mt][nt][half * 2 + 0] + bv.x;
                    float v1 = acc[mt][nt][half * 2 + 1] + bv.y;
                    float2 o;
                    o.x = (((int)xs.x & 1) == 0) ? v0 : -v0;
                    o.y = (((int)xs.y & 1) == 0) ? v1 : -v1;
                    *(float2*)&Kout[(size_t)m * DD + n0] = o;
                }
            }
        }
    }
}

// ---------------- combine + speculative split + fused decide ----------------
__global__ void k_combine() {
    if (g_done) return;
    const float dt = g_dt;
    const int cur = g_cur;
    const float B1 = (float)(16.0 / 135.0),  B3 = (float)(6656.0 / 12825.0);
    const float B4 = (float)(28561.0 / 56430.0), B5 = (float)(-9.0 / 50.0), B6 = (float)(2.0 / 55.0);
    const float C1 = (float)(25.0 / 216.0),  C3 = (float)(1408.0 / 2565.0);
    const float C4 = (float)(2197.0 / 4104.0), C5 = (float)(-1.0 / 5.0);

    const float4* SRC = (const float4*)(cur ? g_X5 : g_X);
    float4*       DST = (float4*)(cur ? g_X : g_X5);
    __nv_bfloat16* AhD = g_AhX[cur ^ 1];
    __nv_bfloat16* AlD = g_AlX[cur ^ 1];

    int i = blockIdx.x * blockDim.x + threadIdx.x;
    float4 x  = SRC[i];
    float4 k1 = ((const float4*)g_K[0])[i];
    float4 k3 = ((const float4*)g_K[2])[i];
    float4 k4 = ((const float4*)g_K[3])[i];
    float4 k5 = ((const float4*)g_K[4])[i];
    float4 k6 = ((const float4*)g_K[5])[i];
    float xx[4] = {x.x, x.y, x.z, x.w};
    float a1[4] = {k1.x, k1.y, k1.z, k1.w};
    float a3[4] = {k3.x, k3.y, k3.z, k3.w};
    float a4[4] = {k4.x, k4.y, k4.z, k4.w};
    float a5[4] = {k5.x, k5.y, k5.z, k5.w};
    float a6[4] = {k6.x, k6.y, k6.z, k6.w};
    float x5[4];
    float emax = 0.0f, smax = 0.0f;
    __nv_bfloat16 h[4], l[4];
#pragma unroll
    for (int c = 0; c < 4; c++) {
        float s5 = B1 * a1[c] + B3 * a3[c] + B4 * a4[c] + B5 * a5[c] + B6 * a6[c];
        float s4 = C1 * a1[c] + C3 * a3[c] + C4 * a4[c] + C5 * a5[c];
        x5[c] = xx[c] + dt * s5;
        float x4v = xx[c] + dt * s4;
        emax = fmaxf(emax, fabsf(x5[c] - x4v));
        smax = fmaxf(smax, fabsf(x5[c] - xx[c]));
        split_bf16(reflect_f(x5[c]), h[c], l[c]);
    }
    float4 o; o.x = x5[0]; o.y = x5[1]; o.z = x5[2]; o.w = x5[3];
    DST[i] = o;
    *(uint2*)&AhD[i * 4] = *(uint2*)h;
    *(uint2*)&AlD[i * 4] = *(uint2*)l;

#pragma unroll
    for (int off = 16; off > 0; off >>= 1) {
        emax = fmaxf(emax, __shfl_xor_sync(0xffffffffu, emax, off));
        smax = fmaxf(smax, __shfl_xor_sync(0xffffffffu, smax, off));
    }
    if ((threadIdx.x & 31) == 0) {
        atomicMax(&g_err_bits, __float_as_uint(emax));
        atomicMax(&g_spd_bits, __float_as_uint(smax));
    }
    __syncthreads();

    if (threadIdx.x == 0) {
        __threadfence();
        unsigned int old = atomicAdd(&g_cnt, 1u);
        if (old == gridDim.x - 1) {
            // ---- fused decide (runs once, after all blocks) ----
            float err = __uint_as_float(atomicMax(&g_err_bits, 0u));
            float spd = __uint_as_float(atomicMax(&g_spd_bits, 0u));
            float dtc = g_dt;
            int accept = (err < TOLC) ? 1 : 0;
            int ncur = g_cur;
            if (accept) {
                ncur ^= 1;
                g_cur = ncur;
                if ((spd / dtc) < SPEED_TOL) g_done = 1;
            }
            g_pAh = g_AhX[ncur];
            g_pAl = g_AlX[ncur];
            g_pXS = ncur ? g_X5 : g_X;
            float scale = 0.9f * powf(TOLC / (err + 1e-12f), 0.2f);
            scale = fminf(fmaxf(scale, 0.1f), 4.0f);
            g_dt = fmaxf(dtc * scale, MIN_DT);
            g_err_bits = 0u; g_spd_bits = 0u; g_cnt = 0u;
        }
    }
}

// ---------------- output ----------------
__global__ void k_final(float* __restrict__ out) {
    const float4* SRC = (const float4*)(g_cur ? g_X5 : g_X);
    int i = blockIdx.x * blockDim.x + threadIdx.x;
    ((float4*)out)[i] = SRC[i];
}

// ---------------- launch ----------------
extern "C" void kernel_launch(void* const* d_in, const int* in_sizes, int n_in,
                              void* d_out, int out_size) {
    const float* x0   = (const float*)d_in[0];
    const float* W    = (const float*)d_in[1];
    const float* bias = (const float*)d_in[2];
    float* out = (float*)d_out;

    cudaFuncSetAttribute(k_gemm_pvf, cudaFuncAttributeMaxDynamicSharedMemorySize, GEMM_SMEM);

    dim3 ggrid(DD / BNT, BD / BMT);  // (32, 4) = 128 CTAs

    k_splitW<<<WV / EW_BLK, EW_BLK>>>(W);
    k_init<<<EW_GRID, EW_BLK>>>(x0);

    for (int step = 0; step < MAX_STEPS; step++) {
        // k1: uses pre-split reflect(current x)
        k_gemm_pvf<<<ggrid, 512, GEMM_SMEM>>>(bias, 0, 1);

        k_stage<1><<<EW_GRID, EW_BLK>>>(0.25f, 0.f, 0.f, 0.f, 0.f);
        k_gemm_pvf<<<ggrid, 512, GEMM_SMEM>>>(bias, 1, 0);

        k_stage<2><<<EW_GRID, EW_BLK>>>((float)(3.0 / 32.0), (float)(9.0 / 32.0), 0.f, 0.f, 0.f);
        k_gemm_pvf<<<ggrid, 512, GEMM_SMEM>>>(bias, 2, 0);

        k_stage<3><<<EW_GRID, EW_BLK>>>((float)(1932.0 / 2197.0), (float)(-7200.0 / 2197.0),
                                        (float)(7296.0 / 2197.0), 0.f, 0.f);
        k_gemm_pvf<<<ggrid, 512, GEMM_SMEM>>>(bias, 3, 0);

        k_stage<4><<<EW_GRID, EW_BLK>>>((float)(439.0 / 216.0), -8.0f, (float)(3680.0 / 513.0),
                                        (float)(-845.0 / 4104.0), 0.f);
        k_gemm_pvf<<<ggrid, 512, GEMM_SMEM>>>(bias, 4, 0);

        k_stage<5><<<EW_GRID, EW_BLK>>>((float)(-8.0 / 27.0), 2.0f, (float)(-3544.0 / 2565.0),
                                        (float)(1859.0 / 4104.0), (float)(-11.0 / 40.0));
        k_gemm_pvf<<<ggrid, 512, GEMM_SMEM>>>(bias, 5, 0);

        k_combine<<<EW_GRID, EW_BLK>>>();
    }

    k_final<<<EW_GRID, EW_BLK>>>(out);
}

// round 6
// speedup vs baseline: 1.3674x; 1.3674x over previous
#include <cuda_runtime.h>
#include <cuda_fp16.h>
#include <cstdint>
#include <math.h>

// ---------------- problem sizes ----------------
#define BD   512
#define DD   2048
#define NTOT (BD*DD)
#define NV   (NTOT/4)      // 262144
#define WTOT (DD*DD)
#define WV   (WTOT/4)

#define MAX_STEPS 32
#define TOLC      0.01f
#define SPEED_TOL 1e-3f
#define DT0       0.1f
#define MIN_DT    0.1f

#define EW_BLK  256
#define EW_GRID (NV / EW_BLK)   // 1024

// ---------------- device state ----------------
__device__ float g_X [NTOT];        // x buffer 0
__device__ float g_X5[NTOT];        // x buffer 1
__device__ float g_SXS[2][NTOT];    // stage-input scratch (fp32, for parity/sign)
__device__ __half g_SA[2][NTOT];    // stage-input scratch split (fp16 A operand)
__device__ __half g_AhX[2][NTOT];   // split of reflect(current x), double buffered
__device__ __half g_Wh[WTOT];
__device__ __half g_Wl[WTOT];
__device__ float g_K [6][NTOT];
__device__ float g_dt;
__device__ int   g_done;
__device__ int   g_cur;
__device__ unsigned int g_err_bits;
__device__ unsigned int g_spd_bits;
__device__ unsigned int g_cnt;
__device__ __half* g_pAh;           // = g_AhX[g_cur]
__device__ float*  g_pX;            // = current x buffer

// ---------------- helpers ----------------
__device__ __forceinline__ float reflect_f(float x) {
    int i = (int)x;
    return ((i & 1) == 0) ? x : 1.0f - x;
}
__device__ __forceinline__ uint32_t smem_u32(const void* p) {
    uint32_t a;
    asm("{ .reg .u64 t; cvta.to.shared.u64 t, %1; cvt.u32.u64 %0, t; }" : "=r"(a) : "l"(p));
    return a;
}
__device__ __forceinline__ void cp16(uint32_t dst, const void* src) {
    asm volatile("cp.async.cg.shared.global [%0], [%1], 16;" :: "r"(dst), "l"(src));
}
__device__ __forceinline__ void cp_commit() { asm volatile("cp.async.commit_group;" ::: "memory"); }
template <int N> __device__ __forceinline__ void cp_wait() {
    asm volatile("cp.async.wait_group %0;" :: "n"(N) : "memory");
}
__device__ __forceinline__ void ldsm4(uint32_t* r, uint32_t addr) {
    asm volatile("ldmatrix.sync.aligned.m8n8.x4.shared.b16 {%0,%1,%2,%3}, [%4];"
                 : "=r"(r[0]), "=r"(r[1]), "=r"(r[2]), "=r"(r[3]) : "r"(addr));
}
__device__ __forceinline__ void mma16816(float* c, const uint32_t* a, const uint32_t* b) {
    asm("mma.sync.aligned.m16n8k16.row.col.f32.f16.f16.f32 "
        "{%0,%1,%2,%3}, {%4,%5,%6,%7}, {%8,%9}, {%0,%1,%2,%3};"
        : "+f"(c[0]), "+f"(c[1]), "+f"(c[2]), "+f"(c[3])
        : "r"(a[0]), "r"(a[1]), "r"(a[2]), "r"(a[3]), "r"(b[0]), "r"(b[1]));
}

// ---------------- init / split ----------------
__global__ void k_splitW(const float* __restrict__ W) {
    int i = blockIdx.x * blockDim.x + threadIdx.x;
    float4 w = ((const float4*)W)[i];
    float v[4] = {w.x, w.y, w.z, w.w};
    __half h[4], l[4];
#pragma unroll
    for (int c = 0; c < 4; c++) {
        h[c] = __float2half_rn(v[c]);
        l[c] = __float2half_rn(v[c] - __half2float(h[c]));
    }
    *(uint2*)&g_Wh[i * 4] = *(uint2*)h;
    *(uint2*)&g_Wl[i * 4] = *(uint2*)l;
}

__global__ void k_init(const float* __restrict__ x0) {
    int i = blockIdx.x * blockDim.x + threadIdx.x;
    float4 x = ((const float4*)x0)[i];
    ((float4*)g_X)[i] = x;
    float v[4] = {x.x, x.y, x.z, x.w};
    __half h[4];
#pragma unroll
    for (int c = 0; c < 4; c++) h[c] = __float2half_rn(reflect_f(v[c]));
    *(uint2*)&g_AhX[0][i * 4] = *(uint2*)h;
    if (i == 0) {
        g_dt = DT0; g_done = 0; g_cur = 0;
        g_err_bits = 0u; g_spd_bits = 0u; g_cnt = 0u;
        g_pAh = g_AhX[0]; g_pX = g_X;
    }
}

// ---------------- fused GEMM + stage prep ----------------
// Stage S (1..6): K[S-1] = sign(XS_S) * (reflect(XS_S) @ W + b)   [A = fp16 split of reflect]
// epilogue also prepares XS_{S+1} = x + dt * sum_{j<=S} a_j K_j and its fp16 split (S<6).
#define BMT 128
#define BNT 64
#define BKC 64
#define NITER (DD / BKC)       // 32
#define PITCH 144
#define BH_OFF (128 * PITCH)                 // 18432
#define BL_OFF (128 * PITCH + 64 * PITCH)    // 27648
#define STAGE  (128 * PITCH + 2 * 64 * PITCH)// 36864
#define GEMM_SMEM (4 * STAGE)                // 147456

__device__ __forceinline__ void load_stage(uint32_t sbase, int k0, int bm, int bn, int tid,
                                           const __half* Ap) {
#pragma unroll
    for (int i = 0; i < 2; i++) {
        int ch = tid + i * 512;          // 1024 chunks: 128 rows x 8
        int r = ch >> 3, c = ch & 7;
        uint32_t off = (uint32_t)(r * PITCH + c * 16);
        cp16(sbase + off, Ap + (size_t)(bm + r) * DD + k0 + c * 8);
    }
    {
        int r = tid >> 3, c = tid & 7;   // 512 chunks: 64 rows x 8
        uint32_t off = (uint32_t)(r * PITCH + c * 16);
        size_t go = (size_t)(bn + r) * DD + k0 + c * 8;
        cp16(sbase + BH_OFF + off, g_Wh + go);
        cp16(sbase + BL_OFF + off, g_Wl + go);
    }
    cp_commit();
}

template <int S>
__global__ __launch_bounds__(512, 1)
void k_gemm(const float* __restrict__ bias) {
    if (g_done) return;
    extern __shared__ char smem[];
    uint32_t sb = smem_u32(smem);
    const int tid  = threadIdx.x;
    const int wid  = tid >> 5;
    const int lane = tid & 31;
    const int wm   = wid >> 2;      // 0..3 -> 32 rows
    const int wn   = wid & 3;       // 0..3 -> 16 cols
    const int bm   = blockIdx.y * BMT;
    const int bn   = blockIdx.x * BNT;

    const __half* Ap = (S == 1) ? g_pAh : g_SA[S & 1];

    float acc[2][2][4];
#pragma unroll
    for (int mt = 0; mt < 2; mt++)
#pragma unroll
        for (int nt = 0; nt < 2; nt++)
#pragma unroll
            for (int c = 0; c < 4; c++) acc[mt][nt][c] = 0.0f;

    load_stage(sb + 0 * STAGE, 0 * BKC, bm, bn, tid, Ap);
    load_stage(sb + 1 * STAGE, 1 * BKC, bm, bn, tid, Ap);
    load_stage(sb + 2 * STAGE, 2 * BKC, bm, bn, tid, Ap);

    const int g  = lane >> 3;
    const int l7 = lane & 7;
    const uint32_t offA0 = (uint32_t)((wm * 32 + ((g & 1) << 3) + l7) * PITCH + (g >> 1) * 16);
    const uint32_t offA1 = offA0 + 16 * PITCH;
    const uint32_t offB  = (uint32_t)((wn * 16 + ((g >> 1) << 3) + l7) * PITCH + (g & 1) * 16);

    for (int it = 0; it < NITER; ++it) {
        if (it < NITER - 2)       cp_wait<2>();
        else if (it == NITER - 2) cp_wait<1>();
        else                      cp_wait<0>();
        __syncthreads();

        int J = it + 3;
        if (J < NITER) load_stage(sb + (uint32_t)((J & 3) * STAGE), J * BKC, bm, bn, tid, Ap);

        uint32_t stg = sb + (uint32_t)((it & 3) * STAGE);
#pragma unroll
        for (int s = 0; s < 4; s++) {
            uint32_t koff = (uint32_t)(s * 32);
            uint32_t a0[4], a1[4], bh[4], bl[4];
            ldsm4(a0, stg + offA0 + koff);
            ldsm4(a1, stg + offA1 + koff);
            ldsm4(bh, stg + BH_OFF + offB + koff);
            ldsm4(bl, stg + BL_OFF + offB + koff);
            mma16816(acc[0][0], a0, &bh[0]);
            mma16816(acc[0][0], a0, &bl[0]);
            mma16816(acc[0][1], a0, &bh[2]);
            mma16816(acc[0][1], a0, &bl[2]);
            mma16816(acc[1][0], a1, &bh[0]);
            mma16816(acc[1][0], a1, &bl[0]);
            mma16816(acc[1][1], a1, &bh[2]);
            mma16816(acc[1][1], a1, &bl[2]);
        }
    }

    // ---- epilogue: K[S-1] + fused next-stage prep ----
    // coefficients a_j of XS_{S+1} = x + dt * sum_{j=1..S} a_j K_j
    const float c1 = (S==1)?0.25f : (S==2)?(float)(3.0/32.0) : (S==3)?(float)(1932.0/2197.0)
                   : (S==4)?(float)(439.0/216.0) : (float)(-8.0/27.0);
    const float c2 = (S==2)?(float)(9.0/32.0) : (S==3)?(float)(-7200.0/2197.0)
                   : (S==4)?-8.0f : 2.0f;
    const float c3 = (S==3)?(float)(7296.0/2197.0) : (S==4)?(float)(3680.0/513.0)
                   : (float)(-3544.0/2565.0);
    const float c4 = (S==4)?(float)(-845.0/4104.0) : (float)(1859.0/4104.0);
    const float c5 = (float)(-11.0/40.0);
    const float cS = (S==1)?c1 : (S==2)?c2 : (S==3)?c3 : (S==4)?c4 : c5;

    const float* Xc   = g_pX;
    const float* XSin = (S == 1) ? g_pX : g_SXS[S & 1];
    float*  Kout = g_K[S - 1];
    float*  XSo  = g_SXS[(S + 1) & 1];
    __half* Ao   = g_SA[(S + 1) & 1];
    const float dt = g_dt;

#pragma unroll
    for (int mt = 0; mt < 2; mt++) {
        int m0 = bm + wm * 32 + mt * 16 + (lane >> 2);
#pragma unroll
        for (int nt = 0; nt < 2; nt++) {
            int n0 = bn + wn * 16 + nt * 8 + 2 * (lane & 3);
            float2 bv = *(const float2*)&bias[n0];
#pragma unroll
            for (int h = 0; h < 2; h++) {
                int m = m0 + h * 8;
                size_t idx = (size_t)m * DD + n0;
                float2 xsin = *(const float2*)&XSin[idx];
                float v0 = acc[mt][nt][h * 2 + 0] + bv.x;
                float v1 = acc[mt][nt][h * 2 + 1] + bv.y;
                float k0v = (((int)xsin.x & 1) == 0) ? v0 : -v0;
                float k1v = (((int)xsin.y & 1) == 0) ? v1 : -v1;
                *(float2*)&Kout[idx] = make_float2(k0v, k1v);
                if (S < 6) {
                    float s0 = cS * k0v, s1 = cS * k1v;
                    if (S >= 2) { float2 k = *(const float2*)&g_K[0][idx]; s0 += c1 * k.x; s1 += c1 * k.y; }
                    if (S >= 3) { float2 k = *(const float2*)&g_K[1][idx]; s0 += c2 * k.x; s1 += c2 * k.y; }
                    if (S >= 4) { float2 k = *(const float2*)&g_K[2][idx]; s0 += c3 * k.x; s1 += c3 * k.y; }
                    if (S >= 5) { float2 k = *(const float2*)&g_K[3][idx]; s0 += c4 * k.x; s1 += c4 * k.y; }
                    float2 xc = *(const float2*)&Xc[idx];
                    float nx0 = xc.x + dt * s0;
                    float nx1 = xc.y + dt * s1;
                    *(float2*)&XSo[idx] = make_float2(nx0, nx1);
                    __half hh[2];
                    hh[0] = __float2half_rn(reflect_f(nx0));
                    hh[1] = __float2half_rn(reflect_f(nx1));
                    *(uint32_t*)&Ao[idx] = *(uint32_t*)hh;
                }
            }
        }
    }
}

// ---------------- combine + speculative split + fused decide ----------------
__global__ void k_combine() {
    if (g_done) return;
    const float dt = g_dt;
    const int cur = g_cur;
    const float B1 = (float)(16.0 / 135.0),  B3 = (float)(6656.0 / 12825.0);
    const float B4 = (float)(28561.0 / 56430.0), B5 = (float)(-9.0 / 50.0), B6 = (float)(2.0 / 55.0);
    const float C1 = (float)(25.0 / 216.0),  C3 = (float)(1408.0 / 2565.0);
    const float C4 = (float)(2197.0 / 4104.0), C5 = (float)(-1.0 / 5.0);

    const float4* SRC = (const float4*)(cur ? g_X5 : g_X);
    float4*       DST = (float4*)(cur ? g_X : g_X5);
    __half* AhD = g_AhX[cur ^ 1];

    int i = blockIdx.x * blockDim.x + threadIdx.x;
    float4 x  = SRC[i];
    float4 k1 = ((const float4*)g_K[0])[i];
    float4 k3 = ((const float4*)g_K[2])[i];
    float4 k4 = ((const float4*)g_K[3])[i];
    float4 k5 = ((const float4*)g_K[4])[i];
    float4 k6 = ((const float4*)g_K[5])[i];
    float xx[4] = {x.x, x.y, x.z, x.w};
    float a1[4] = {k1.x, k1.y, k1.z, k1.w};
    float a3[4] = {k3.x, k3.y, k3.z, k3.w};
    float a4[4] = {k4.x, k4.y, k4.z, k4.w};
    float a5[4] = {k5.x, k5.y, k5.z, k5.w};
    float a6[4] = {k6.x, k6.y, k6.z, k6.w};
    float x5[4];
    float emax = 0.0f, smax = 0.0f;
    __half hh[4];
#pragma unroll
    for (int c = 0; c < 4; c++) {
        float s5 = B1 * a1[c] + B3 * a3[c] + B4 * a4[c] + B5 * a5[c] + B6 * a6[c];
        float s4 = C1 * a1[c] + C3 * a3[c] + C4 * a4[c] + C5 * a5[c];
        x5[c] = xx[c] + dt * s5;
        float x4v = xx[c] + dt * s4;
        emax = fmaxf(emax, fabsf(x5[c] - x4v));
        smax = fmaxf(smax, fabsf(x5[c] - xx[c]));
        hh[c] = __float2half_rn(reflect_f(x5[c]));
    }
    float4 o; o.x = x5[0]; o.y = x5[1]; o.z = x5[2]; o.w = x5[3];
    DST[i] = o;
    *(uint2*)&AhD[i * 4] = *(uint2*)hh;

#pragma unroll
    for (int off = 16; off > 0; off >>= 1) {
        emax = fmaxf(emax, __shfl_xor_sync(0xffffffffu, emax, off));
        smax = fmaxf(smax, __shfl_xor_sync(0xffffffffu, smax, off));
    }
    if ((threadIdx.x & 31) == 0) {
        atomicMax(&g_err_bits, __float_as_uint(emax));
        atomicMax(&g_spd_bits, __float_as_uint(smax));
    }
    __syncthreads();

    if (threadIdx.x == 0) {
        __threadfence();
        unsigned int old = atomicAdd(&g_cnt, 1u);
        if (old == gridDim.x - 1) {
            float err = __uint_as_float(atomicMax(&g_err_bits, 0u));
            float spd = __uint_as_float(atomicMax(&g_spd_bits, 0u));
            float dtc = g_dt;
            int accept = (err < TOLC) ? 1 : 0;
            int ncur = g_cur;
            if (accept) {
                ncur ^= 1;
                g_cur = ncur;
                if ((spd / dtc) < SPEED_TOL) g_done = 1;
            }
            g_pAh = g_AhX[ncur];
            g_pX  = ncur ? g_X5 : g_X;
            float scale = 0.9f * powf(TOLC / (err + 1e-12f), 0.2f);
            scale = fminf(fmaxf(scale, 0.1f), 4.0f);
            g_dt = fmaxf(dtc * scale, MIN_DT);
            g_err_bits = 0u; g_spd_bits = 0u; g_cnt = 0u;
        }
    }
}

// ---------------- output ----------------
__global__ void k_final(float* __restrict__ out) {
    const float4* SRC = (const float4*)(g_cur ? g_X5 : g_X);
    int i = blockIdx.x * blockDim.x + threadIdx.x;
    ((float4*)out)[i] = SRC[i];
}

// ---------------- launch ----------------
extern "C" void kernel_launch(void* const* d_in, const int* in_sizes, int n_in,
                              void* d_out, int out_size) {
    const float* x0   = (const float*)d_in[0];
    const float* W    = (const float*)d_in[1];
    const float* bias = (const float*)d_in[2];
    float* out = (float*)d_out;

    cudaFuncSetAttribute(k_gemm<1>, cudaFuncAttributeMaxDynamicSharedMemorySize, GEMM_SMEM);
    cudaFuncSetAttribute(k_gemm<2>, cudaFuncAttributeMaxDynamicSharedMemorySize, GEMM_SMEM);
    cudaFuncSetAttribute(k_gemm<3>, cudaFuncAttributeMaxDynamicSharedMemorySize, GEMM_SMEM);
    cudaFuncSetAttribute(k_gemm<4>, cudaFuncAttributeMaxDynamicSharedMemorySize, GEMM_SMEM);
    cudaFuncSetAttribute(k_gemm<5>, cudaFuncAttributeMaxDynamicSharedMemorySize, GEMM_SMEM);
    cudaFuncSetAttribute(k_gemm<6>, cudaFuncAttributeMaxDynamicSharedMemorySize, GEMM_SMEM);

    dim3 ggrid(DD / BNT, BD / BMT);  // (32, 4) = 128 CTAs

    k_splitW<<<WV / EW_BLK, EW_BLK>>>(W);
    k_init<<<EW_GRID, EW_BLK>>>(x0);

    for (int step = 0; step < MAX_STEPS; step++) {
        k_gemm<1><<<ggrid, 512, GEMM_SMEM>>>(bias);
        k_gemm<2><<<ggrid, 512, GEMM_SMEM>>>(bias);
        k_gemm<3><<<ggrid, 512, GEMM_SMEM>>>(bias);
        k_gemm<4><<<ggrid, 512, GEMM_SMEM>>>(bias);
        k_gemm<5><<<ggrid, 512, GEMM_SMEM>>>(bias);
        k_gemm<6><<<ggrid, 512, GEMM_SMEM>>>(bias);
        k_combine<<<EW_GRID, EW_BLK>>>();
    }

    k_final<<<EW_GRID, EW_BLK>>>(out);
}